// round 2
// baseline (speedup 1.0000x reference)
#include <cuda_runtime.h>
#include <stdint.h>

#define KPRE       500
#define MAXDET     300
#define SCORE_THR  0.05f
#define NMS_THR    0.5f
#define MIN_SIZE   0.01f
#define BBOX_CLAMP 4.135166556742356f   // log(1000/16)

#define SAMPLE     4                     // sample every 4th anchor for estimation
#define EST_TARGET 250u                  // sample-count target (-> ~1000 actual)
#define CAPG       4096                  // per-class candidate buffer
#define STCAP      4096                  // per-block staging
#define CHUNKA     1024                  // anchors per collect block
#define NT5        512
#define DYN_SMEM5  40768                 // keys/ioum 32KB (aliased) + cbox 8KB

#define BMAX   2
#define AMAX   131072
#define CMAX   96
#define BCMAX  192
#define ASMAX  32768

__device__ float              g_boxes[(size_t)BMAX * AMAX * 4];
__device__ unsigned char      g_valid[(size_t)BMAX * AMAX];
__device__ float              g_ssc[(size_t)BMAX * CMAX * ASMAX];   // sampled transposed scores
__device__ unsigned long long g_keys[(size_t)BCMAX * CAPG];
__device__ float              g_T[BCMAX];
__device__ unsigned int       g_cnt[BCMAX];
__device__ unsigned int       g_flag[BCMAX];

// ---------------------------------------------------------------------------
// K1: decode + clamp + valid mask
// ---------------------------------------------------------------------------
__global__ void rn_decode_kernel(const float* __restrict__ deltas,
                                 const float* __restrict__ anchors,
                                 const int* __restrict__ imh,
                                 const int* __restrict__ imw,
                                 int B, int A) {
    int i = blockIdx.x * blockDim.x + threadIdx.x;
    if (i >= B * A) return;
    float W = (float)imw[0];
    float H = (float)imh[0];
    float4 an = reinterpret_cast<const float4*>(anchors)[i];
    float4 dt = reinterpret_cast<const float4*>(deltas)[i];
    float aw  = an.z - an.x;
    float ah  = an.w - an.y;
    float acx = an.x + 0.5f * aw;
    float acy = an.y + 0.5f * ah;
    float dw  = fminf(dt.z, BBOX_CLAMP);
    float dh  = fminf(dt.w, BBOX_CLAMP);
    float pcx = dt.x * aw + acx;
    float pcy = dt.y * ah + acy;
    float pw  = expf(dw) * aw;
    float ph  = expf(dh) * ah;
    float x1 = fminf(fmaxf(pcx - 0.5f * pw, 0.0f), W);
    float y1 = fminf(fmaxf(pcy - 0.5f * ph, 0.0f), H);
    float x2 = fminf(fmaxf(pcx + 0.5f * pw, 0.0f), W);
    float y2 = fminf(fmaxf(pcy + 0.5f * ph, 0.0f), H);
    reinterpret_cast<float4*>(g_boxes)[i] = make_float4(x1, y1, x2, y2);
    g_valid[i] = (((x2 - x1) >= MIN_SIZE) && ((y2 - y1) >= MIN_SIZE)) ? 1 : 0;
}

// ---------------------------------------------------------------------------
// K2a: sampled transpose [B, A(sampled), C] -> [B, C, AS] with mask folded
// ---------------------------------------------------------------------------
__global__ void rn_sample_transpose(const float* __restrict__ scores,
                                    int B, int A, int C, int AS) {
    __shared__ float tile[32][33];
    int b  = blockIdx.z;
    int s0 = blockIdx.x * 32;
    int c0 = blockIdx.y * 32;

    #pragma unroll
    for (int r = 0; r < 32; r += 8) {
        int as = s0 + threadIdx.y + r;
        int c  = c0 + threadIdx.x;
        int a  = as * SAMPLE;
        float v = -1.0f;
        if (as < AS && a < A && c < C) {
            float s = scores[((size_t)b * A + a) * (size_t)C + c];
            if (g_valid[(size_t)b * A + a] && s > SCORE_THR) v = s;
        }
        tile[threadIdx.y + r][threadIdx.x] = v;
    }
    __syncthreads();

    int as = s0 + threadIdx.x;
    #pragma unroll
    for (int r = 0; r < 32; r += 8) {
        int c = c0 + threadIdx.y + r;
        if (as < AS && c < C)
            g_ssc[((size_t)b * C + c) * (size_t)AS + as] = tile[threadIdx.x][threadIdx.y + r];
    }
}

// ---------------------------------------------------------------------------
// K2b: per-(b,c) threshold estimation: 3 rounds of 16-edge ladder counting
// (no atomics in the hot loop). Also zeroes g_cnt / g_flag.
// ---------------------------------------------------------------------------
__global__ void __launch_bounds__(512)
rn_estimate(int B, int C, int AS) {
    int bc = blockIdx.x;
    const float* __restrict__ col = g_ssc + (size_t)bc * AS;
    __shared__ float s_lo, s_hi;
    __shared__ unsigned int s_part[16][16];   // [warp][edge]
    int tid = threadIdx.x;
    int w = tid >> 5, l = tid & 31;

    if (tid == 0) { s_lo = SCORE_THR; s_hi = 1.0f; }
    __syncthreads();

    for (int pass = 0; pass < 3; pass++) {
        float lo = s_lo, hi = s_hi;
        float step = (hi - lo) * (1.0f / 17.0f);
        float e[16];
        #pragma unroll
        for (int k = 0; k < 16; k++) e[k] = lo + step * (float)(k + 1);

        unsigned int cnt[16];
        #pragma unroll
        for (int k = 0; k < 16; k++) cnt[k] = 0;

        for (int i = tid; i < AS; i += 512) {
            float s = col[i];
            #pragma unroll
            for (int k = 0; k < 16; k++) cnt[k] += (s > e[k]) ? 1u : 0u;
        }
        #pragma unroll
        for (int k = 0; k < 16; k++) {
            #pragma unroll
            for (int o = 16; o > 0; o >>= 1)
                cnt[k] += __shfl_down_sync(0xFFFFFFFFu, cnt[k], o);
        }
        if (l == 0) {
            #pragma unroll
            for (int k = 0; k < 16; k++) s_part[w][k] = cnt[k];
        }
        __syncthreads();
        if (tid == 0) {
            unsigned int tot[16];
            for (int k = 0; k < 16; k++) {
                unsigned int t = 0;
                for (int ww = 0; ww < 16; ww++) t += s_part[ww][k];
                tot[k] = t;
            }
            int kstar = -1;
            for (int k = 15; k >= 0; k--)
                if (tot[k] >= EST_TARGET) { kstar = k; break; }
            if (kstar >= 0) {
                s_lo = e[kstar];
                s_hi = (kstar < 15) ? e[kstar + 1] : hi;
            } else {
                s_hi = e[0];   // quantile below lowest edge: shrink from above
            }
        }
        __syncthreads();
    }
    if (tid == 0) {
        g_T[bc]    = s_lo;   // == SCORE_THR exactly if never raised
        g_cnt[bc]  = 0;
        g_flag[bc] = 0;
    }
}

// ---------------------------------------------------------------------------
// K4: full coalesced pass over scores; collect candidates (s > T) into
// per-class global key buffers via SMEM staging + block reservation.
// ---------------------------------------------------------------------------
__device__ __forceinline__ void rn_push(float s, int c, int a_loc,
                                        unsigned int* s_ccnt, unsigned int* s_n,
                                        unsigned int* s_sc, unsigned int* s_meta,
                                        int* s_ovf) {
    unsigned int lp = atomicAdd(&s_ccnt[c], 1u);
    unsigned int p  = atomicAdd(s_n, 1u);
    if (p < STCAP) {
        s_sc[p]   = __float_as_uint(s);
        s_meta[p] = ((unsigned int)c << 20) | (lp << 10) | (unsigned int)a_loc;
    } else {
        *s_ovf = 1;
    }
}

__global__ void __launch_bounds__(256)
rn_collect(const float* __restrict__ scores, int B, int A, int C) {
    int b  = blockIdx.y;
    int a0 = blockIdx.x * CHUNKA;
    int na = min(CHUNKA, A - a0);

    __shared__ float         s_T[CMAX];
    __shared__ unsigned char sval[CHUNKA];
    __shared__ unsigned int  s_sc[STCAP];
    __shared__ unsigned int  s_meta[STCAP];
    __shared__ unsigned int  s_ccnt[CMAX];
    __shared__ unsigned int  s_base[CMAX];
    __shared__ unsigned int  s_n;
    __shared__ int           s_ovf;

    int tid = threadIdx.x;
    for (int c = tid; c < C; c += 256) {
        s_T[c]    = fmaxf(g_T[b * C + c], SCORE_THR);
        s_ccnt[c] = 0;
    }
    for (int i = tid; i < na; i += 256)
        sval[i] = g_valid[(size_t)b * A + a0 + i];
    if (tid == 0) { s_n = 0; s_ovf = 0; }
    __syncthreads();

    const float* __restrict__ base = scores + ((size_t)b * A + a0) * (size_t)C;

    if ((C & 3) == 0) {
        int n4 = na * C / 4;
        int stepa = (256 * 4) / C;
        int stepc = (256 * 4) - stepa * C;
        int idx0 = tid * 4;
        int a = idx0 / C;
        int c = idx0 - a * C;
        const float4* __restrict__ b4 = reinterpret_cast<const float4*>(base);
        for (int i = tid; i < n4; i += 256) {
            float4 v = b4[i];
            if (sval[a]) {
                if (v.x > s_T[c + 0]) rn_push(v.x, c + 0, a, s_ccnt, &s_n, s_sc, s_meta, &s_ovf);
                if (v.y > s_T[c + 1]) rn_push(v.y, c + 1, a, s_ccnt, &s_n, s_sc, s_meta, &s_ovf);
                if (v.z > s_T[c + 2]) rn_push(v.z, c + 2, a, s_ccnt, &s_n, s_sc, s_meta, &s_ovf);
                if (v.w > s_T[c + 3]) rn_push(v.w, c + 3, a, s_ccnt, &s_n, s_sc, s_meta, &s_ovf);
            }
            a += stepa; c += stepc;
            if (c >= C) { c -= C; a++; }
        }
    } else {
        int nE = na * C;
        for (int i = tid; i < nE; i += 256) {
            int a = i / C;
            int c = i - a * C;
            float s = base[i];
            if (sval[a] && s > s_T[c])
                rn_push(s, c, a, s_ccnt, &s_n, s_sc, s_meta, &s_ovf);
        }
    }
    __syncthreads();

    if (s_ovf) {   // staging overflow: flag everything in this image for exact fixup
        for (int c = tid; c < C; c += 256) g_flag[b * C + c] = 1;
        return;
    }
    for (int c = tid; c < C; c += 256)
        if (s_ccnt[c]) s_base[c] = atomicAdd(&g_cnt[b * C + c], s_ccnt[c]);
    __syncthreads();

    unsigned int nn = min(s_n, (unsigned int)STCAP);
    for (unsigned int i = tid; i < nn; i += 256) {
        unsigned int m  = s_meta[i];
        int c           = (int)(m >> 20);
        unsigned int lp = (m >> 10) & 1023u;
        unsigned int al = m & 1023u;
        unsigned int pos = s_base[c] + lp;
        if (pos < CAPG) {
            unsigned int ag = (unsigned int)a0 + al;
            g_keys[(size_t)(b * C + c) * CAPG + pos] =
                ((unsigned long long)s_sc[i] << 32) |
                (unsigned long long)(0xFFFFFFFFu - ag);
        } else {
            g_flag[b * C + c] = 1;   // class buffer overflow -> exact fixup
        }
    }
}

// ---------------------------------------------------------------------------
// K4b: exact fallback for flagged/undercounted classes (strided, rare)
// ---------------------------------------------------------------------------
#define FBINS 8192
__global__ void __launch_bounds__(512)
rn_fixup(const float* __restrict__ scores, int B, int A, int C) {
    __shared__ int s_go;
    int bc  = blockIdx.x;
    int tid = threadIdx.x;
    if (tid == 0)
        s_go = (g_flag[bc] != 0) || (g_cnt[bc] < KPRE && g_T[bc] > SCORE_THR);
    __syncthreads();
    if (!s_go) return;

    int b = bc / C;
    int c = bc % C;
    __shared__ unsigned int hist[FBINS];
    __shared__ unsigned int chunk[512];
    __shared__ unsigned int s_T, s_cnt;

    for (int i = tid; i < FBINS; i += 512) hist[i] = 0;
    if (tid == 0) s_cnt = 0;
    __syncthreads();

    for (int a = tid; a < A; a += 512) {
        float s = scores[((size_t)b * A + a) * (size_t)C + c];
        if (g_valid[(size_t)b * A + a] && s > SCORE_THR) {
            int bin = min(max((int)(s * (float)FBINS), 0), FBINS - 1);
            atomicAdd(&hist[bin], 1u);
        }
    }
    __syncthreads();
    {
        unsigned int cs = 0;
        const int per = FBINS / 512;
        #pragma unroll
        for (int i = 0; i < FBINS / 512; i++) cs += hist[tid * per + i];
        chunk[tid] = cs;
    }
    __syncthreads();
    if (tid == 0) {
        const int per = FBINS / 512;
        unsigned int cum = 0;
        int cc;
        for (cc = 511; cc >= 0; cc--) {
            if (cum + chunk[cc] >= KPRE) break;
            cum += chunk[cc];
        }
        int T = 0;
        if (cc >= 0) {
            int bs = cc * per;
            for (int bb = bs + per - 1; bb >= bs; bb--) {
                cum += hist[bb];
                if (cum >= KPRE) { T = bb; break; }
            }
        }
        s_T = (unsigned int)T;
    }
    __syncthreads();
    unsigned int T = s_T;

    for (int a = tid; a < A; a += 512) {
        float s = scores[((size_t)b * A + a) * (size_t)C + c];
        if (g_valid[(size_t)b * A + a] && s > SCORE_THR) {
            unsigned int bin = (unsigned int)min((int)(s * (float)FBINS), FBINS - 1);
            if (bin >= T) {
                unsigned int pos = atomicAdd(&s_cnt, 1u);
                if (pos < CAPG)
                    g_keys[(size_t)bc * CAPG + pos] =
                        ((unsigned long long)__float_as_uint(s) << 32) |
                        (unsigned long long)(0xFFFFFFFFu - (unsigned int)a);
            }
        }
    }
    __syncthreads();
    if (tid == 0) g_cnt[bc] = min(s_cnt, (unsigned int)CAPG);
}

// ---------------------------------------------------------------------------
// K5: per-class sort + NMS + output
// ---------------------------------------------------------------------------
__global__ void __launch_bounds__(NT5)
rn_nms(float* __restrict__ out, int B, int A, int C) {
    extern __shared__ unsigned char dyn[];
    unsigned long long* keys  = reinterpret_cast<unsigned long long*>(dyn);  // [<=4096]
    unsigned int*       ioum  = reinterpret_cast<unsigned int*>(dyn);        // alias
    float4*             cbox4 = reinterpret_cast<float4*>(dyn + 32768);      // [KPRE]

    __shared__ float cscore[KPRE];
    __shared__ unsigned int s_nkeep;
    __shared__ unsigned int keep0[16], keepw[16], pref[16];

    const int tid = threadIdx.x;
    const int bc  = blockIdx.x;
    const int b   = bc / C;

    unsigned int n = min(g_cnt[bc], (unsigned int)CAPG);
    const int NSORT = (n <= 2048u) ? 2048 : 4096;
    const unsigned long long* __restrict__ gk = g_keys + (size_t)bc * CAPG;

    for (int i = tid; i < NSORT; i += NT5)
        keys[i] = (i < (int)n) ? gk[i] : 0ULL;
    if (tid < 16) keep0[tid] = 0;
    __syncthreads();

    for (int k = 2; k <= NSORT; k <<= 1) {
        for (int j = k >> 1; j > 0; j >>= 1) {
            for (int i = tid; i < NSORT; i += NT5) {
                int ixj = i ^ j;
                if (ixj > i) {
                    unsigned long long x = keys[i];
                    unsigned long long y = keys[ixj];
                    bool desc = ((i & k) == 0);
                    if (desc ? (x < y) : (x > y)) { keys[i] = y; keys[ixj] = x; }
                }
            }
            __syncthreads();
        }
    }

    // candidate setup
    if (tid < KPRE) {
        unsigned long long key = keys[tid];
        float s = __uint_as_float((unsigned int)(key >> 32));
        unsigned int aidx = 0xFFFFFFFFu - (unsigned int)(key & 0xFFFFFFFFull);
        bool cv = (s > SCORE_THR);
        cscore[tid] = s;
        float4 bx = make_float4(0.0f, 0.0f, 0.0f, 0.0f);
        if (cv) bx = reinterpret_cast<const float4*>(g_boxes)[(size_t)b * A + aidx];
        cbox4[tid] = bx;
        if (cv) atomicOr(&keep0[tid >> 5], 1u << (tid & 31));
    }
    __syncthreads();   // keys no longer needed; ioum may overwrite

    // IoU suppression bitmask
    for (int w = tid; w < KPRE * 16; w += NT5) {
        int i  = w >> 4;
        int wi = w & 15;
        float4 bi = cbox4[i];
        float iarea = (bi.z - bi.x) * (bi.w - bi.y);
        unsigned int m = 0;
        int jbase = wi * 32;
        #pragma unroll 4
        for (int bit = 0; bit < 32; bit++) {
            int j = jbase + bit;
            if (j < KPRE && j > i) {
                float4 bj = cbox4[j];
                float jarea = (bj.z - bj.x) * (bj.w - bj.y);
                float lx = fmaxf(bi.x, bj.x);
                float ly = fmaxf(bi.y, bj.y);
                float rx = fminf(bi.z, bj.z);
                float ry = fminf(bi.w, bj.w);
                float iw = fmaxf(rx - lx, 0.0f);
                float ih = fmaxf(ry - ly, 0.0f);
                float inter = iw * ih;
                float iou = inter / fmaxf(iarea + jarea - inter, 1e-9f);
                if (iou > NMS_THR) m |= (1u << bit);
            }
        }
        ioum[w] = m;
    }
    __syncthreads();

    // serial-semantics NMS scan (16 lanes own one keep-word each)
    if (tid < 16) {
        unsigned int kw = keep0[tid];
        for (int i = 0; i < KPRE; i++) {
            unsigned int word = __shfl_sync(0xFFFFu, kw, i >> 5);
            if ((word >> (i & 31)) & 1u)
                kw &= ~ioum[i * 16 + tid];
        }
        keepw[tid] = kw;
        unsigned int p = __popc(kw);
        unsigned int scan = p;
        #pragma unroll
        for (int o = 1; o < 16; o <<= 1) {
            unsigned int v = __shfl_up_sync(0xFFFFu, scan, o);
            if (tid >= o) scan += v;
        }
        pref[tid] = scan - p;
        if (tid == 15) s_nkeep = scan;
    }
    __syncthreads();

    float* outp = out + (size_t)bc * MAXDET * 5;
    if (tid < KPRE) {
        unsigned int kw = keepw[tid >> 5];
        if ((kw >> (tid & 31)) & 1u) {
            unsigned int rank = pref[tid >> 5] + __popc(kw & ((1u << (tid & 31)) - 1u));
            if (rank < MAXDET) {
                float4 bx = cbox4[tid];
                outp[rank * 5 + 0] = bx.x;
                outp[rank * 5 + 1] = bx.y;
                outp[rank * 5 + 2] = bx.z;
                outp[rank * 5 + 3] = bx.w;
                outp[rank * 5 + 4] = cscore[tid];
            }
        }
    }
    unsigned int nk = min(s_nkeep, (unsigned int)MAXDET);
    for (int r = (int)nk + tid; r < MAXDET; r += NT5) {
        outp[r * 5 + 0] = 0.0f;
        outp[r * 5 + 1] = 0.0f;
        outp[r * 5 + 2] = 0.0f;
        outp[r * 5 + 3] = 0.0f;
        outp[r * 5 + 4] = -1.0f;
    }
}

// ---------------------------------------------------------------------------
// host launch
// ---------------------------------------------------------------------------
extern "C" void kernel_launch(void* const* d_in, const int* in_sizes, int n_in,
                              void* d_out, int out_size) {
    const float* deltas  = (const float*)d_in[0];
    const float* scores  = (const float*)d_in[1];
    const float* anchors = (const float*)d_in[2];
    const int*   imh     = (const int*)d_in[3];
    const int*   imw     = (const int*)d_in[4];

    long long nd = in_sizes[0];
    long long ns = in_sizes[1];
    int C  = (int)(ns * 4 / nd);
    int BC = out_size / (MAXDET * 5);
    int B  = BC / C;
    int A  = (int)(nd / (4LL * B));
    int AS = (A + SAMPLE - 1) / SAMPLE;

    float* out = (float*)d_out;

    int n = B * A;
    rn_decode_kernel<<<(n + 255) / 256, 256>>>(deltas, anchors, imh, imw, B, A);

    dim3 tb(32, 8);
    dim3 tg((AS + 31) / 32, (C + 31) / 32, B);
    rn_sample_transpose<<<tg, tb>>>(scores, B, A, C, AS);

    rn_estimate<<<B * C, 512>>>(B, C, AS);

    dim3 cg((A + CHUNKA - 1) / CHUNKA, B);
    rn_collect<<<cg, 256>>>(scores, B, A, C);

    rn_fixup<<<B * C, 512>>>(scores, B, A, C);

    cudaFuncSetAttribute(rn_nms, cudaFuncAttributeMaxDynamicSharedMemorySize, DYN_SMEM5);
    rn_nms<<<B * C, NT5, DYN_SMEM5>>>(out, B, A, C);
}

// round 3
// speedup vs baseline: 1.2171x; 1.2171x over previous
#include <cuda_runtime.h>
#include <stdint.h>

#define KPRE       500
#define MAXDET     300
#define SCORE_THR  0.05f
#define NMS_THR    0.5f
#define MIN_SIZE   0.01f
#define BBOX_CLAMP 4.135166556742356f   // log(1000/16)

#define HBINS      64
#define HLO        0.9f
#define HSCALE     640.0f                // HBINS / (1 - HLO)
#define HBINW      0.0015625f            // (1-HLO)/HBINS
#define CAPG       4096
#define NT5        512
#define DYN_SMEM5  40768                 // keys(<=32KB, aliased by ioum 32000B) + cbox 8000B

#define BMAX   2
#define AMAX   131072
#define CMAX   96
#define BCMAX  192

__device__ float              g_boxes[(size_t)BMAX * AMAX * 4];
__device__ unsigned char      g_valid[(size_t)BMAX * AMAX];
__device__ unsigned int       g_hist[(size_t)BCMAX * HBINS];
__device__ unsigned long long g_keys[(size_t)BCMAX * CAPG];
__device__ float              g_T[BCMAX];
__device__ unsigned int       g_cnt[BCMAX];
__device__ unsigned int       g_flag[BCMAX];

// ---------------------------------------------------------------------------
// K1: decode + clamp + valid mask; also zero global counters/hist
// ---------------------------------------------------------------------------
__global__ void rn_decode_kernel(const float* __restrict__ deltas,
                                 const float* __restrict__ anchors,
                                 const int* __restrict__ imh,
                                 const int* __restrict__ imw,
                                 int B, int A) {
    int i = blockIdx.x * blockDim.x + threadIdx.x;
    if (i < BCMAX * HBINS) g_hist[i] = 0;
    if (i < BCMAX) { g_cnt[i] = 0; g_flag[i] = 0; }
    if (i >= B * A) return;
    float W = (float)imw[0];
    float H = (float)imh[0];
    float4 an = reinterpret_cast<const float4*>(anchors)[i];
    float4 dt = reinterpret_cast<const float4*>(deltas)[i];
    float aw  = an.z - an.x;
    float ah  = an.w - an.y;
    float acx = an.x + 0.5f * aw;
    float acy = an.y + 0.5f * ah;
    float dw  = fminf(dt.z, BBOX_CLAMP);
    float dh  = fminf(dt.w, BBOX_CLAMP);
    float pcx = dt.x * aw + acx;
    float pcy = dt.y * ah + acy;
    float pw  = expf(dw) * aw;
    float ph  = expf(dh) * ah;
    float x1 = fminf(fmaxf(pcx - 0.5f * pw, 0.0f), W);
    float y1 = fminf(fmaxf(pcy - 0.5f * ph, 0.0f), H);
    float x2 = fminf(fmaxf(pcx + 0.5f * pw, 0.0f), W);
    float y2 = fminf(fmaxf(pcy + 0.5f * ph, 0.0f), H);
    reinterpret_cast<float4*>(g_boxes)[i] = make_float4(x1, y1, x2, y2);
    g_valid[i] = (((x2 - x1) >= MIN_SIZE) && ((y2 - y1) >= MIN_SIZE)) ? 1 : 0;
}

// ---------------------------------------------------------------------------
// K2: coalesced histogram of scores > HLO into per-(b,c) 64-bin smem hist
// ---------------------------------------------------------------------------
#define HNT   512
#define HWORK 40960   // float4s per block (C%4==0 path)

__global__ void __launch_bounds__(HNT)
rn_hist(const float* __restrict__ scores, int B, int A, int C) {
    extern __shared__ unsigned int sh[];   // [C * HBINS]
    int b   = blockIdx.y;
    int tid = threadIdx.x;
    for (int i = tid; i < C * HBINS; i += HNT) sh[i] = 0;
    __syncthreads();

    const unsigned char* __restrict__ val = g_valid + (size_t)b * A;

    if ((C & 3) == 0) {
        int C4 = C >> 2;
        const float4* __restrict__ s4 =
            reinterpret_cast<const float4*>(scores + (size_t)b * A * C);
        long long i0  = (long long)blockIdx.x * HWORK;
        long long end = (long long)A * C4;
        long long lim = min(i0 + (long long)HWORK, end);
        for (long long i = i0 + tid; i < lim; i += HNT) {
            float4 v = s4[i];
            int a  = (int)(i / C4);
            int c4 = (int)(i - (long long)a * C4) << 2;
            if (val[a]) {
                if (v.x > HLO) atomicAdd(&sh[(c4 + 0) * HBINS + min((int)((v.x - HLO) * HSCALE), HBINS - 1)], 1u);
                if (v.y > HLO) atomicAdd(&sh[(c4 + 1) * HBINS + min((int)((v.y - HLO) * HSCALE), HBINS - 1)], 1u);
                if (v.z > HLO) atomicAdd(&sh[(c4 + 2) * HBINS + min((int)((v.z - HLO) * HSCALE), HBINS - 1)], 1u);
                if (v.w > HLO) atomicAdd(&sh[(c4 + 3) * HBINS + min((int)((v.w - HLO) * HSCALE), HBINS - 1)], 1u);
            }
        }
    } else {
        const float* __restrict__ s1 = scores + (size_t)b * A * C;
        long long i0  = (long long)blockIdx.x * (HWORK * 4);
        long long end = (long long)A * C;
        long long lim = min(i0 + (long long)(HWORK * 4), end);
        for (long long i = i0 + tid; i < lim; i += HNT) {
            float s = s1[i];
            int a = (int)(i / C);
            int c = (int)(i - (long long)a * C);
            if (val[a] && s > HLO)
                atomicAdd(&sh[c * HBINS + min((int)((s - HLO) * HSCALE), HBINS - 1)], 1u);
        }
    }
    __syncthreads();
    for (int i = tid; i < C * HBINS; i += HNT)
        if (sh[i]) atomicAdd(&g_hist[(size_t)b * C * HBINS + i], sh[i]);
}

// ---------------------------------------------------------------------------
// K3: per-class threshold from hist suffix scan
// ---------------------------------------------------------------------------
__global__ void rn_thresh(int BC) {
    int bc = blockIdx.x * blockDim.x + threadIdx.x;
    if (bc >= BC) return;
    const unsigned int* h = g_hist + (size_t)bc * HBINS;
    unsigned int cum = 0;
    int kk = -1;
    for (int k = HBINS - 1; k >= 0; k--) {
        cum += h[k];
        if (cum >= KPRE) { kk = k; break; }
    }
    g_T[bc] = (kk >= 0) ? (HLO + (float)kk * HBINW) : SCORE_THR;
}

// ---------------------------------------------------------------------------
// K4: coalesced collect pass: s > T[c] -> key into per-class global buffer
// ---------------------------------------------------------------------------
#define CNT   256
#define CWORK 4096    // float4s per block

__device__ __forceinline__ void rn_push_g(float s, int bc, unsigned int a) {
    unsigned int pos = atomicAdd(&g_cnt[bc], 1u);
    if (pos < CAPG)
        g_keys[(size_t)bc * CAPG + pos] =
            ((unsigned long long)__float_as_uint(s) << 32) |
            (unsigned long long)(0xFFFFFFFFu - a);
    else
        g_flag[bc] = 1;
}

__global__ void __launch_bounds__(CNT)
rn_collect(const float* __restrict__ scores, int B, int A, int C) {
    __shared__ float s_T[CMAX];
    int b   = blockIdx.y;
    int tid = threadIdx.x;
    for (int c = tid; c < C; c += CNT) s_T[c] = g_T[b * C + c];
    __syncthreads();

    const unsigned char* __restrict__ val = g_valid + (size_t)b * A;

    if ((C & 3) == 0) {
        int C4 = C >> 2;
        const float4* __restrict__ s4 =
            reinterpret_cast<const float4*>(scores + (size_t)b * A * C);
        long long i0  = (long long)blockIdx.x * CWORK;
        long long end = (long long)A * C4;
        long long lim = min(i0 + (long long)CWORK, end);
        for (long long i = i0 + tid; i < lim; i += CNT) {
            float4 v = s4[i];
            int a  = (int)(i / C4);
            int c4 = (int)(i - (long long)a * C4) << 2;
            if (val[a]) {
                if (v.x > s_T[c4 + 0]) rn_push_g(v.x, b * C + c4 + 0, (unsigned int)a);
                if (v.y > s_T[c4 + 1]) rn_push_g(v.y, b * C + c4 + 1, (unsigned int)a);
                if (v.z > s_T[c4 + 2]) rn_push_g(v.z, b * C + c4 + 2, (unsigned int)a);
                if (v.w > s_T[c4 + 3]) rn_push_g(v.w, b * C + c4 + 3, (unsigned int)a);
            }
        }
    } else {
        const float* __restrict__ s1 = scores + (size_t)b * A * C;
        long long i0  = (long long)blockIdx.x * (CWORK * 4);
        long long end = (long long)A * C;
        long long lim = min(i0 + (long long)(CWORK * 4), end);
        for (long long i = i0 + tid; i < lim; i += CNT) {
            float s = s1[i];
            int a = (int)(i / C);
            int c = (int)(i - (long long)a * C);
            if (val[a] && s > s_T[c]) rn_push_g(s, b * C + c, (unsigned int)a);
        }
    }
}

// ---------------------------------------------------------------------------
// K5: exact fallback for flagged/undercounted classes (strided, rare)
// ---------------------------------------------------------------------------
#define FBINS 8192
__global__ void __launch_bounds__(512)
rn_fixup(const float* __restrict__ scores, int B, int A, int C) {
    __shared__ int s_go;
    int bc  = blockIdx.x;
    int tid = threadIdx.x;
    if (tid == 0)
        s_go = (g_flag[bc] != 0) ||
               (g_cnt[bc] < KPRE && g_T[bc] > SCORE_THR);
    __syncthreads();
    if (!s_go) return;

    int b = bc / C;
    int c = bc % C;
    __shared__ unsigned int hist[FBINS];
    __shared__ unsigned int chunk[512];
    __shared__ unsigned int s_T, s_cnt;

    for (int i = tid; i < FBINS; i += 512) hist[i] = 0;
    if (tid == 0) s_cnt = 0;
    __syncthreads();

    for (int a = tid; a < A; a += 512) {
        float s = scores[((size_t)b * A + a) * (size_t)C + c];
        if (g_valid[(size_t)b * A + a] && s > SCORE_THR) {
            int bin = min(max((int)(s * (float)FBINS), 0), FBINS - 1);
            atomicAdd(&hist[bin], 1u);
        }
    }
    __syncthreads();
    {
        unsigned int cs = 0;
        const int per = FBINS / 512;
        #pragma unroll
        for (int i = 0; i < FBINS / 512; i++) cs += hist[tid * per + i];
        chunk[tid] = cs;
    }
    __syncthreads();
    if (tid == 0) {
        const int per = FBINS / 512;
        unsigned int cum = 0;
        int cc;
        for (cc = 511; cc >= 0; cc--) {
            if (cum + chunk[cc] >= KPRE) break;
            cum += chunk[cc];
        }
        int T = 0;
        if (cc >= 0) {
            int bs = cc * per;
            for (int bb = bs + per - 1; bb >= bs; bb--) {
                cum += hist[bb];
                if (cum >= KPRE) { T = bb; break; }
            }
        }
        s_T = (unsigned int)T;
    }
    __syncthreads();
    unsigned int T = s_T;

    for (int a = tid; a < A; a += 512) {
        float s = scores[((size_t)b * A + a) * (size_t)C + c];
        if (g_valid[(size_t)b * A + a] && s > SCORE_THR) {
            unsigned int bin = (unsigned int)min((int)(s * (float)FBINS), FBINS - 1);
            if (bin >= T) {
                unsigned int pos = atomicAdd(&s_cnt, 1u);
                if (pos < CAPG)
                    g_keys[(size_t)bc * CAPG + pos] =
                        ((unsigned long long)__float_as_uint(s) << 32) |
                        (unsigned long long)(0xFFFFFFFFu - (unsigned int)a);
            }
        }
    }
    __syncthreads();
    if (tid == 0) g_cnt[bc] = min(s_cnt, (unsigned int)CAPG);
}

// ---------------------------------------------------------------------------
// K6: per-class sort + NMS + output
// ---------------------------------------------------------------------------
__global__ void __launch_bounds__(NT5)
rn_nms(float* __restrict__ out, int B, int A, int C) {
    extern __shared__ unsigned char dyn[];
    unsigned long long* keys  = reinterpret_cast<unsigned long long*>(dyn);  // [<=4096]
    unsigned int*       ioum  = reinterpret_cast<unsigned int*>(dyn);        // alias, 32000B
    float4*             cbox4 = reinterpret_cast<float4*>(dyn + 32768);      // [KPRE]

    __shared__ float cscore[KPRE];
    __shared__ unsigned int s_nkeep;
    __shared__ unsigned int keep0[16], keepw[16], pref[16];

    const int tid = threadIdx.x;
    const int bc  = blockIdx.x;
    const int b   = bc / C;

    unsigned int n = min(g_cnt[bc], (unsigned int)CAPG);
    int NSORT = 1024;
    while ((unsigned int)NSORT < n) NSORT <<= 1;   // 1024/2048/4096
    const unsigned long long* __restrict__ gk = g_keys + (size_t)bc * CAPG;

    for (int i = tid; i < NSORT; i += NT5)
        keys[i] = (i < (int)n) ? gk[i] : 0ULL;
    if (tid < 16) keep0[tid] = 0;
    __syncthreads();

    for (int k = 2; k <= NSORT; k <<= 1) {
        for (int j = k >> 1; j > 0; j >>= 1) {
            for (int i = tid; i < NSORT; i += NT5) {
                int ixj = i ^ j;
                if (ixj > i) {
                    unsigned long long x = keys[i];
                    unsigned long long y = keys[ixj];
                    bool desc = ((i & k) == 0);
                    if (desc ? (x < y) : (x > y)) { keys[i] = y; keys[ixj] = x; }
                }
            }
            __syncthreads();
        }
    }

    if (tid < KPRE) {
        unsigned long long key = keys[tid];
        float s = __uint_as_float((unsigned int)(key >> 32));
        unsigned int aidx = 0xFFFFFFFFu - (unsigned int)(key & 0xFFFFFFFFull);
        bool cv = (s > SCORE_THR);
        cscore[tid] = s;
        float4 bx = make_float4(0.0f, 0.0f, 0.0f, 0.0f);
        if (cv) bx = reinterpret_cast<const float4*>(g_boxes)[(size_t)b * A + aidx];
        cbox4[tid] = bx;
        if (cv) atomicOr(&keep0[tid >> 5], 1u << (tid & 31));
    }
    __syncthreads();   // keys done; ioum may overwrite

    for (int w = tid; w < KPRE * 16; w += NT5) {
        int i  = w >> 4;
        int wi = w & 15;
        float4 bi = cbox4[i];
        float iarea = (bi.z - bi.x) * (bi.w - bi.y);
        unsigned int m = 0;
        int jbase = wi * 32;
        #pragma unroll 4
        for (int bit = 0; bit < 32; bit++) {
            int j = jbase + bit;
            if (j < KPRE && j > i) {
                float4 bj = cbox4[j];
                float jarea = (bj.z - bj.x) * (bj.w - bj.y);
                float lx = fmaxf(bi.x, bj.x);
                float ly = fmaxf(bi.y, bj.y);
                float rx = fminf(bi.z, bj.z);
                float ry = fminf(bi.w, bj.w);
                float iw = fmaxf(rx - lx, 0.0f);
                float ih = fmaxf(ry - ly, 0.0f);
                float inter = iw * ih;
                float iou = inter / fmaxf(iarea + jarea - inter, 1e-9f);
                if (iou > NMS_THR) m |= (1u << bit);
            }
        }
        ioum[w] = m;
    }
    __syncthreads();

    if (tid < 16) {
        unsigned int kw = keep0[tid];
        for (int i = 0; i < KPRE; i++) {
            unsigned int word = __shfl_sync(0xFFFFu, kw, i >> 5);
            if ((word >> (i & 31)) & 1u)
                kw &= ~ioum[i * 16 + tid];
        }
        keepw[tid] = kw;
        unsigned int p = __popc(kw);
        unsigned int scan = p;
        #pragma unroll
        for (int o = 1; o < 16; o <<= 1) {
            unsigned int v = __shfl_up_sync(0xFFFFu, scan, o);
            if (tid >= o) scan += v;
        }
        pref[tid] = scan - p;
        if (tid == 15) s_nkeep = scan;
    }
    __syncthreads();

    float* outp = out + (size_t)bc * MAXDET * 5;
    if (tid < KPRE) {
        unsigned int kw = keepw[tid >> 5];
        if ((kw >> (tid & 31)) & 1u) {
            unsigned int rank = pref[tid >> 5] + __popc(kw & ((1u << (tid & 31)) - 1u));
            if (rank < MAXDET) {
                float4 bx = cbox4[tid];
                outp[rank * 5 + 0] = bx.x;
                outp[rank * 5 + 1] = bx.y;
                outp[rank * 5 + 2] = bx.z;
                outp[rank * 5 + 3] = bx.w;
                outp[rank * 5 + 4] = cscore[tid];
            }
        }
    }
    unsigned int nk = min(s_nkeep, (unsigned int)MAXDET);
    for (int r = (int)nk + tid; r < MAXDET; r += NT5) {
        outp[r * 5 + 0] = 0.0f;
        outp[r * 5 + 1] = 0.0f;
        outp[r * 5 + 2] = 0.0f;
        outp[r * 5 + 3] = 0.0f;
        outp[r * 5 + 4] = -1.0f;
    }
}

// ---------------------------------------------------------------------------
// host launch
// ---------------------------------------------------------------------------
extern "C" void kernel_launch(void* const* d_in, const int* in_sizes, int n_in,
                              void* d_out, int out_size) {
    const float* deltas  = (const float*)d_in[0];
    const float* scores  = (const float*)d_in[1];
    const float* anchors = (const float*)d_in[2];
    const int*   imh     = (const int*)d_in[3];
    const int*   imw     = (const int*)d_in[4];

    long long nd = in_sizes[0];
    long long ns = in_sizes[1];
    int C  = (int)(ns * 4 / nd);
    int BC = out_size / (MAXDET * 5);
    int B  = BC / C;
    int A  = (int)(nd / (4LL * B));

    float* out = (float*)d_out;

    int n = B * A;
    rn_decode_kernel<<<(n + 255) / 256, 256>>>(deltas, anchors, imh, imw, B, A);

    long long totE = (long long)A * C;
    long long tot4 = ((C & 3) == 0) ? totE / 4 : totE;

    int hb = (int)((tot4 + (HWORK - 1)) / HWORK);          // elems unit ok both paths
    if ((C & 3) != 0) hb = (int)((tot4 + (HWORK * 4 - 1)) / (HWORK * 4));
    cudaFuncSetAttribute(rn_hist, cudaFuncAttributeMaxDynamicSharedMemorySize,
                         CMAX * HBINS * 4);
    rn_hist<<<dim3(hb, B), HNT, C * HBINS * 4>>>(scores, B, A, C);

    rn_thresh<<<(BC + 127) / 128, 128>>>(BC);

    int cb = ((C & 3) == 0) ? (int)((tot4 + (CWORK - 1)) / CWORK)
                            : (int)((tot4 + (CWORK * 4 - 1)) / (CWORK * 4));
    rn_collect<<<dim3(cb, B), CNT>>>(scores, B, A, C);

    rn_fixup<<<BC, 512>>>(scores, B, A, C);

    cudaFuncSetAttribute(rn_nms, cudaFuncAttributeMaxDynamicSharedMemorySize, DYN_SMEM5);
    rn_nms<<<BC, NT5, DYN_SMEM5>>>(out, B, A, C);
}